// round 6
// baseline (speedup 1.0000x reference)
#include <cuda_runtime.h>
#include <cooperative_groups.h>
namespace cg = cooperative_groups;

// Problem constants (fixed by the reference)
#define B       32
#define N       2048
#define OUTD    100
#define CLSZ    8                    // cluster size = j-splits
#define JCHUNK  (N / CLSZ)           // 256
#define BPG     2                    // batch rows per block
#define BGROUPS (B / BPG)            // 16 clusters
#define GRID    (BGROUPS * CLSZ)     // 128 blocks
#define NT      512
#define NW      16
#define JPW     (JCHUNK / NW)        // 16 j per warp

// Reference: out[b,o] = sum_j rem[b,j] W[j,o],
//   rem[b,j] = (q - (N*c + S_b))^2, c = (int)q, S_b = sum_j c (exact ints < 2^24)
// Expansion with e = q - N*c (block-local):
//   out[b,o] = A - 2*S_b*B + S_b^2*C,  A = sum e^2 W, B = sum e W, C = sum_j W.
// Split partials are exchanged via DSMEM within a cluster (fixed peer order ->
// deterministic). No global atomics, no threadfence, single launch.

struct Smem {
    float2 ep[BPG][JCHUNK];        // (e, e^2)           4 KB
    float2 part[NW][BPG * OUTD];   // per-warp (A,B)    25.6 KB
    float  cpart[NW][OUTD];        // per-warp C         6.4 KB
    int    qsum[NW];
    // published to cluster peers:
    float2 blkAB[BPG * OUTD];      // 1.6 KB
    float  blkC[OUTD];
    int    blkS[BPG];
};

__global__ void __cluster_dims__(CLSZ, 1, 1) __launch_bounds__(NT, 1)
fused_rowstat_cluster_kernel(const float* __restrict__ q,
                             const float* __restrict__ W,
                             float* __restrict__ out)
{
    __shared__ Smem sm;
    cg::cluster_group cluster = cg::this_cluster();
    const int rank = (int)cluster.block_rank();    // j-split index 0..7
    const int tid  = threadIdx.x;
    const int wid  = tid >> 5;
    const int lane = tid & 31;
    const int bg   = blockIdx.x / CLSZ;            // batch group 0..15
    const int j0   = rank * JCHUNK;

    // ---- Prefetch W slice into registers (independent of q path) ----
    const int g  = lane;                 // g<25 owns outputs 4g..4g+3
    const int jw = wid * JPW;
    float4 w4[JPW];
    if (g < 25) {
        const float* Wg = W + (size_t)(j0 + jw) * OUTD + g * 4;
        #pragma unroll
        for (int jj = 0; jj < JPW; ++jj)
            w4[jj] = *reinterpret_cast<const float4*>(Wg + jj * OUTD);
    }

    // ---- Load q chunk (1 float/thread), build (e,e^2), int partial sums ----
    {
        const int r   = tid >> 8;        // row 0: warps 0-7, row 1: warps 8-15
        const int col = tid & 255;
        float qv = q[(size_t)(bg * BPG + r) * N + j0 + col];
        int   c  = (int)qv;              // trunc == astype(int32)
        float e  = qv - (float)(N * c);
        sm.ep[r][col] = make_float2(e, e * e);

        int ss = c;
        #pragma unroll
        for (int o = 16; o > 0; o >>= 1) ss += __shfl_xor_sync(0xFFFFFFFFu, ss, o);
        if (lane == 0) sm.qsum[wid] = ss;
    }
    __syncthreads();

    // ---- GEMV: A, B, C on registers + smem broadcast (scalar FFMA) ----
    if (g < 25) {
        float aA[BPG][4], aB[BPG][4], aC[4] = {0.f, 0.f, 0.f, 0.f};
        #pragma unroll
        for (int r = 0; r < BPG; ++r)
            #pragma unroll
            for (int k = 0; k < 4; ++k) { aA[r][k] = 0.f; aB[r][k] = 0.f; }

        #pragma unroll
        for (int jj = 0; jj < JPW; ++jj) {
            const int col = jw + jj;
            const float4 w  = w4[jj];
            const float2 e0 = sm.ep[0][col];
            const float2 e1 = sm.ep[1][col];
            aC[0] += w.x; aC[1] += w.y; aC[2] += w.z; aC[3] += w.w;
            aA[0][0]=fmaf(e0.y,w.x,aA[0][0]); aA[0][1]=fmaf(e0.y,w.y,aA[0][1]);
            aA[0][2]=fmaf(e0.y,w.z,aA[0][2]); aA[0][3]=fmaf(e0.y,w.w,aA[0][3]);
            aB[0][0]=fmaf(e0.x,w.x,aB[0][0]); aB[0][1]=fmaf(e0.x,w.y,aB[0][1]);
            aB[0][2]=fmaf(e0.x,w.z,aB[0][2]); aB[0][3]=fmaf(e0.x,w.w,aB[0][3]);
            aA[1][0]=fmaf(e1.y,w.x,aA[1][0]); aA[1][1]=fmaf(e1.y,w.y,aA[1][1]);
            aA[1][2]=fmaf(e1.y,w.z,aA[1][2]); aA[1][3]=fmaf(e1.y,w.w,aA[1][3]);
            aB[1][0]=fmaf(e1.x,w.x,aB[1][0]); aB[1][1]=fmaf(e1.x,w.y,aB[1][1]);
            aB[1][2]=fmaf(e1.x,w.z,aB[1][2]); aB[1][3]=fmaf(e1.x,w.w,aB[1][3]);
        }
        #pragma unroll
        for (int r = 0; r < BPG; ++r)
            #pragma unroll
            for (int k = 0; k < 4; ++k)
                sm.part[wid][r * OUTD + 4 * g + k] = make_float2(aA[r][k], aB[r][k]);
        *reinterpret_cast<float4*>(&sm.cpart[wid][4 * g]) =
            make_float4(aC[0], aC[1], aC[2], aC[3]);
    }
    __syncthreads();

    // ---- Reduce across 16 warps into the published block partials ----
    if (tid < BPG * OUTD) {                          // 200 threads: (A,B)
        float A = 0.f, Bv = 0.f;
        #pragma unroll
        for (int w = 0; w < NW; ++w) {
            float2 v = sm.part[w][tid];
            A += v.x; Bv += v.y;
        }
        sm.blkAB[tid] = make_float2(A, Bv);
    } else if (tid >= 256 && tid < 256 + OUTD) {     // 100 threads: C
        const int o = tid - 256;
        float C = 0.f;
        #pragma unroll
        for (int w = 0; w < NW; ++w) C += sm.cpart[w][o];
        sm.blkC[o] = C;
    } else if (tid >= 384 && tid < 384 + BPG) {      // 2 threads: S
        const int r = tid - 384;
        int S = 0;
        #pragma unroll
        for (int w = 0; w < 8; ++w) S += sm.qsum[r * 8 + w];
        sm.blkS[r] = S;
    }

    // ---- Exchange partials within the cluster (release/acquire via sync) ----
    cluster.sync();

    // ---- Each rank combines 25 of the cluster's 200 outputs ----
    if (tid < 25) {
        const int idx = rank * 25 + tid;             // 0..199
        const int rr  = idx / OUTD;
        const int o   = idx - rr * OUTD;
        float A = 0.f, Bv = 0.f, C = 0.f;
        int   S = 0;
        #pragma unroll
        for (int p = 0; p < CLSZ; ++p) {             // fixed order -> deterministic
            const Smem* rp = cluster.map_shared_rank(&sm, p);
            float2 ab = rp->blkAB[idx];
            A += ab.x; Bv += ab.y;
            C += rp->blkC[o];
            S += rp->blkS[rr];
        }
        const float Sf = (float)S;                   // exact int
        out[(bg * BPG + rr) * OUTD + o] = fmaf(Sf * Sf, C, fmaf(-2.f * Sf, Bv, A));
    }

    // Keep smem alive until all peers finished reading it.
    cluster.sync();
}

extern "C" void kernel_launch(void* const* d_in, const int* in_sizes, int n_in,
                              void* d_out, int out_size)
{
    const float* q = (const float*)d_in[0];   // [32, 2048] f32
    const float* W = (const float*)d_in[1];   // [2048, 100] f32
    float* out = (float*)d_out;               // [32, 100] f32
    (void)in_sizes; (void)n_in; (void)out_size;

    fused_rowstat_cluster_kernel<<<GRID, NT>>>(q, W, out);
}

// round 7
// speedup vs baseline: 1.4154x; 1.4154x over previous
#include <cuda_runtime.h>

// Problem constants (fixed by the reference)
#define B       32
#define N       2048
#define OUTD    100
#define JSPLITS 16
#define JCHUNK  (N / JSPLITS)        // 128
#define BPG     4                    // batch rows per block (W register reuse)
#define BGROUPS (B / BPG)            // 8
#define GRID    (JSPLITS * BGROUPS)  // 128 blocks
#define NT      512
#define NW      16
#define J_PER_WARP (JCHUNK / NW)     // 8

// out[b,o] = sum_j rem[b,j] * W[j,o]
// rem[b,j] = (q[b,j] - float(N*c[b,j] + S_b))^2, c = (int)q, S_b = sum_j c[b,j]
// Exact vs reference: all integer partials < 2^24, so the reference's fp32
// reduce of the [N,N] broadcast equals the int32 closed form bit-for-bit.

__device__ float        g_partial[JSPLITS][B][OUTD];
__device__ unsigned int g_count[BGROUPS];            // zero-initialized

__global__ __launch_bounds__(NT, 1)
void fused_rowstat_gemv_kernel(const float* __restrict__ q,
                               const float* __restrict__ W,
                               float* __restrict__ out)
{
    __shared__ __align__(16) float4 rem4[BPG][JCHUNK / 4];   // 2 KB
    __shared__ float  part_sh[NW][BPG * OUTD];               // 25.6 KB
    __shared__ int    qsum[NW];
    __shared__ int    S_sh[BPG];
    __shared__ int    last_flag;

    const int tid  = threadIdx.x;
    const int wid  = tid >> 5;
    const int lane = tid & 31;
    const int s    = blockIdx.x & (JSPLITS - 1);   // j-split index
    const int bg   = blockIdx.x >> 4;              // batch-group index
    const int j0   = s * JCHUNK;

    // ---- Prefetch W into registers (block-index-dependent only). Eight
    //      independent LDG.128 retire behind the q-load/reduce phases. ----
    const int g  = lane;                 // output group: o = 4g..4g+3 (g<25)
    const int jw = wid * J_PER_WARP;
    float4 w4[J_PER_WARP];
    if (g < 25) {
        const float* Wg = W + (size_t)(j0 + jw) * OUTD + g * 4;
        #pragma unroll
        for (int jj = 0; jj < J_PER_WARP; ++jj)
            w4[jj] = *reinterpret_cast<const float4*>(Wg + jj * OUTD);
    }

    // ---- Phase 1: int row-sums for the 4 rows (4 warps per row); keep the
    //      float4 that belongs to this block's j-chunk in a register. ----
    const int r       = wid >> 2;                  // row within group
    const int quarter = wid & 3;
    const int i_need  = s >> 2;                    // unroll step holding chunk s
    const bool owns_chunk = (quarter == (s & 3));
    float4 vkeep;
    {
        const float4* q4 = reinterpret_cast<const float4*>(q + (bg * BPG + r) * N);
        const int t = quarter * 32 + lane;         // 0..127
        int ss = 0;
        #pragma unroll
        for (int i = 0; i < 4; ++i) {
            float4 v = q4[t + 128 * i];
            ss += (int)v.x + (int)v.y + (int)v.z + (int)v.w;
            if (i == i_need) vkeep = v;
        }
        ss = __reduce_add_sync(0xFFFFFFFFu, ss);   // REDUX.SUM
        if (lane == 0) qsum[wid] = ss;
    }
    __syncthreads();
    if (tid < BPG)
        S_sh[tid] = qsum[4*tid] + qsum[4*tid+1] + qsum[4*tid+2] + qsum[4*tid+3];
    __syncthreads();

    // ---- Phase 2: rem chunk straight from registers (no q reload) ----
    if (owns_chunk) {
        const int   S = S_sh[r];
        const float4 v = vkeep;
        int   c0 = (int)v.x, c1 = (int)v.y, c2 = (int)v.z, c3 = (int)v.w;
        float d0 = v.x - (float)(N * c0 + S);
        float d1 = v.y - (float)(N * c1 + S);
        float d2 = v.z - (float)(N * c2 + S);
        float d3 = v.w - (float)(N * c3 + S);
        rem4[r][lane] = make_float4(d0*d0, d1*d1, d2*d2, d3*d3);
    }
    __syncthreads();

    // ---- Phase 3: GEMV, fully register-resident.
    //      Per row: 2 broadcast LDS.128 pull the warp's 8 rem values, then
    //      the jj loop is pure FFMA on registers. ----
    if (g < 25) {
        const int f4 = wid * 2;                    // float4 index of jw
        #pragma unroll
        for (int rr = 0; rr < BPG; ++rr) {
            float4 rm0 = rem4[rr][f4];             // rem[jw..jw+3] (broadcast)
            float4 rm1 = rem4[rr][f4 + 1];         // rem[jw+4..jw+7]
            float rv[8] = { rm0.x, rm0.y, rm0.z, rm0.w,
                            rm1.x, rm1.y, rm1.z, rm1.w };
            float a0 = 0.f, a1 = 0.f, a2 = 0.f, a3 = 0.f;
            #pragma unroll
            for (int jj = 0; jj < J_PER_WARP; ++jj) {
                a0 = fmaf(rv[jj], w4[jj].x, a0);
                a1 = fmaf(rv[jj], w4[jj].y, a1);
                a2 = fmaf(rv[jj], w4[jj].z, a2);
                a3 = fmaf(rv[jj], w4[jj].w, a3);
            }
            *reinterpret_cast<float4*>(&part_sh[wid][rr * OUTD + g * 4]) =
                make_float4(a0, a1, a2, a3);
        }
    }
    __syncthreads();

    // ---- Phase 4: reduce 16 warps, publish split-K partial (plain STG) ----
    if (tid < BPG * OUTD) {                        // 400 of 512 threads
        float ssum = 0.f;
        #pragma unroll
        for (int w = 0; w < NW; ++w) ssum += part_sh[w][tid];
        const int rr = tid / OUTD;
        const int o  = tid - rr * OUTD;
        g_partial[s][bg * BPG + rr][o] = ssum;
    }
    __syncthreads();

    // ---- Phase 5: acq_rel counter — release orders our partial stores,
    //      acquire orders the winner's drain loads. No threadfence. ----
    if (tid == 0) {
        unsigned old;
        asm volatile("atom.add.acq_rel.gpu.global.u32 %0, [%1], %2;"
                     : "=r"(old)
                     : "l"(&g_count[bg]), "r"(1u)
                     : "memory");
        last_flag = (old == JSPLITS - 1);
        if (last_flag) g_count[bg] = 0;            // self-reset for graph replay
    }
    __syncthreads();

    if (last_flag && tid < BPG * OUTD) {
        const int rr = tid / OUTD;
        const int o  = tid - rr * OUTD;
        const int b  = bg * BPG + rr;
        float ssum = 0.f;
        #pragma unroll
        for (int sp = 0; sp < JSPLITS; ++sp)       // 16 MLP'd loads
            ssum += g_partial[sp][b][o];
        out[b * OUTD + o] = ssum;
    }
}

extern "C" void kernel_launch(void* const* d_in, const int* in_sizes, int n_in,
                              void* d_out, int out_size)
{
    const float* q = (const float*)d_in[0];   // [32, 2048] f32
    const float* W = (const float*)d_in[1];   // [2048, 100] f32
    float* out = (float*)d_out;               // [32, 100] f32
    (void)in_sizes; (void)n_in; (void)out_size;

    fused_rowstat_gemv_kernel<<<GRID, NT>>>(q, W, out);
}